// round 1
// baseline (speedup 1.0000x reference)
#include <cuda_runtime.h>

// ---------------- problem constants ----------------
#define Bc    16
#define Nc    512
#define Lc    1024
#define Hc    4
#define COMPc 128
#define GATc  64
#define ESMCc 1152
#define HIDc  512

// ---------------- device scratch (static, no runtime alloc) ----------------
__device__ float g_Wh  [16u*4*512*64];      // [B,H,N,GAT]
__device__ float g_s1  [16u*4*512];
__device__ float g_s2  [16u*4*512];
__device__ float g_att1[16u*4*512*512];     // [B,H,N,N]
__device__ float g_multi[16u*512*256];      // [B,N,H*GAT]
__device__ float g_Wh2 [16u*512*128];       // [B,N,COMP]
__device__ float g_t1  [16u*512];
__device__ float g_t2  [16u*512];
__device__ float g_att2[16u*512*512];       // [B,N,N]
__device__ float g_hp2 [16u*512*128];
__device__ float g_hid [16u*1024*512];      // [B,L,HID]

// ---------------- K1: av = emb[atoms]; Wh = av @ W_gat; s1,s2 ----------------
__global__ void k_embed_gat1(const int* __restrict__ atoms,
                             const float* __restrict__ emb_atom,
                             const float* __restrict__ W_gat,
                             const float* __restrict__ a_gat)
{
    __shared__ float av[128];
    __shared__ float r1[8], r2[8];
    int row = blockIdx.x;            // b*512 + n
    int t   = threadIdx.x;           // 256
    if (t < 128) {
        int atom = atoms[row];
        av[t] = emb_atom[atom * 128 + t];
    }
    __syncthreads();
    int h = t >> 6, f = t & 63;
    const float* Wp = W_gat + (h * 128) * 64 + f;
    float acc = 0.f;
#pragma unroll 8
    for (int c = 0; c < 128; c++) acc += av[c] * Wp[c * 64];
    int b  = row >> 9;
    int n  = row & 511;
    int bh = b * 4 + h;
    g_Wh[((long)bh * 512 + n) * 64 + f] = acc;
    float p1 = acc * a_gat[h * 128 + f];
    float p2 = acc * a_gat[h * 128 + 64 + f];
#pragma unroll
    for (int o = 16; o; o >>= 1) {
        p1 += __shfl_xor_sync(~0u, p1, o);
        p2 += __shfl_xor_sync(~0u, p2, o);
    }
    int w = t >> 5;
    if ((t & 31) == 0) { r1[w] = p1; r2[w] = p2; }
    __syncthreads();
    if ((t & 63) == 0) {
        g_s1[(long)bh * 512 + n] = r1[2 * h] + r1[2 * h + 1];
        g_s2[(long)bh * 512 + n] = r2[2 * h] + r2[2 * h + 1];
    }
}

// ---------------- attention rows: softmax(leaky(s1_i+s2_j) masked) ----------------
// grid.x = B*Hn*N, 256 threads
__global__ void k_att_rows(const float* __restrict__ s1,
                           const float* __restrict__ s2,
                           const int*   __restrict__ adj,
                           float* __restrict__ att, int Hn)
{
    __shared__ float ebuf[512];
    __shared__ float sred[8];
    __shared__ float bc0, bc1;
    int t   = threadIdx.x;           // 256
    int bhn = blockIdx.x;
    int n   = bhn & 511;
    int bh  = bhn >> 9;
    int b   = bh / Hn;
    float s1v = s1[bh * 512 + n];
    const float* s2r = s2 + bh * 512;
    const int*   ar  = adj + ((long)(b * 512 + n)) * 512;

    float mx = -INFINITY;
#pragma unroll
    for (int jj = 0; jj < 2; jj++) {
        int j = t + jj * 256;
        float x = s1v + s2r[j];
        x = x > 0.f ? x : 0.2f * x;
        float e = (ar[j] > 0) ? x : -9e15f;
        ebuf[j] = e;
        mx = fmaxf(mx, e);
    }
#pragma unroll
    for (int o = 16; o; o >>= 1) mx = fmaxf(mx, __shfl_xor_sync(~0u, mx, o));
    if ((t & 31) == 0) sred[t >> 5] = mx;
    __syncthreads();
    if (t < 8) {
        float v = sred[t];
#pragma unroll
        for (int o = 4; o; o >>= 1) v = fmaxf(v, __shfl_xor_sync(0xffu, v, o));
        if (t == 0) bc0 = v;
    }
    __syncthreads();
    mx = bc0;
    float sum = 0.f;
#pragma unroll
    for (int jj = 0; jj < 2; jj++) {
        int j = t + jj * 256;
        float p = __expf(ebuf[j] - mx);
        ebuf[j] = p;
        sum += p;
    }
    __syncthreads();                    // protect sred reuse
#pragma unroll
    for (int o = 16; o; o >>= 1) sum += __shfl_xor_sync(~0u, sum, o);
    if ((t & 31) == 0) sred[t >> 5] = sum;
    __syncthreads();
    if (t < 8) {
        float v = sred[t];
#pragma unroll
        for (int o = 4; o; o >>= 1) v += __shfl_xor_sync(0xffu, v, o);
        if (t == 0) bc1 = v;
    }
    __syncthreads();
    float inv = 1.f / bc1;
    float* arow = att + (long)bhn * 512;
#pragma unroll
    for (int jj = 0; jj < 2; jj++) {
        int j = t + jj * 256;
        arow[j] = ebuf[j] * inv;
    }
}

// ---------------- generic tiled SGEMM with fused epilogues ----------------
// MODE 0: plain batched store      C[bz*M*Nn + m*Nn + n] = x
// MODE 1: relu(x + bias[n])        C[m*Nn + n]
// MODE 2: leaky(x+bias[n]), protein remap into out[b*1536+512+l, n]
// MODE 3: elu(x), multi layout     C[(b*512 + m)*256 + h*64 + n], bz = b*H + h
template<int BM, int BN, int BK, int TM, int TN, int MODE>
__global__ void __launch_bounds__((BM/TM)*(BN/TN))
sgemm_k(const float* __restrict__ A, const float* __restrict__ Bmat,
        const float* __restrict__ bias, float* __restrict__ C,
        int M, int Nn, int K, long sA, long sB)
{
    constexpr int THREADS = (BM / TM) * (BN / TN);
    __shared__ float As[BK][BM];
    __shared__ float Bs[BK][BN];
    int tid = threadIdx.x;
    int bz  = blockIdx.z;
    const float* Ab = A    + (long)bz * sA;
    const float* Bb = Bmat + (long)bz * sB;
    int bm = blockIdx.y * BM, bn = blockIdx.x * BN;
    int tx = tid % (BN / TN);
    int ty = tid / (BN / TN);
    float acc[TM][TN] = {};

    constexpr int A_F4 = BM * BK / 4;
    constexpr int B_F4 = BK * BN / 4;
    constexpr int A_IT = (A_F4 + THREADS - 1) / THREADS;
    constexpr int B_IT = (B_F4 + THREADS - 1) / THREADS;

    for (int k0 = 0; k0 < K; k0 += BK) {
        __syncthreads();
#pragma unroll
        for (int i = 0; i < A_IT; i++) {
            int tt = tid + i * THREADS;
            if (tt < A_F4) {
                int m  = tt / (BK / 4);
                int kv = tt % (BK / 4);
                float4 v = *(const float4*)&Ab[(long)(bm + m) * K + k0 + kv * 4];
                As[kv * 4 + 0][m] = v.x; As[kv * 4 + 1][m] = v.y;
                As[kv * 4 + 2][m] = v.z; As[kv * 4 + 3][m] = v.w;
            }
        }
#pragma unroll
        for (int i = 0; i < B_IT; i++) {
            int tt = tid + i * THREADS;
            if (tt < B_F4) {
                int k  = tt / (BN / 4);
                int nv = tt % (BN / 4);
                *(float4*)&Bs[k][nv * 4] =
                    *(const float4*)&Bb[(long)(k0 + k) * Nn + bn + nv * 4];
            }
        }
        __syncthreads();
#pragma unroll
        for (int k = 0; k < BK; k++) {
            float a[TM], bv[TN];
#pragma unroll
            for (int i = 0; i < TM; i++) a[i] = As[k][ty * TM + i];
#pragma unroll
            for (int j = 0; j < TN; j++) bv[j] = Bs[k][tx * TN + j];
#pragma unroll
            for (int i = 0; i < TM; i++)
#pragma unroll
                for (int j = 0; j < TN; j++) acc[i][j] += a[i] * bv[j];
        }
    }

#pragma unroll
    for (int i = 0; i < TM; i++) {
        int m = bm + ty * TM + i;
#pragma unroll
        for (int j = 0; j < TN; j++) {
            int n = bn + tx * TN + j;
            float x = acc[i][j];
            if (MODE == 0) {
                C[(long)bz * M * Nn + (long)m * Nn + n] = x;
            } else if (MODE == 1) {
                x += bias[n];
                C[(long)m * Nn + n] = fmaxf(x, 0.f);
            } else if (MODE == 2) {
                x += bias[n];
                x = (x >= 0.f) ? x : 0.2f * x;
                int bb = m >> 10;          // / L
                int l  = m & 1023;
                C[((long)(bb * 1536 + 512 + l)) * 128 + n] = x;
            } else { // MODE 3
                x = (x > 0.f) ? x : (__expf(x) - 1.f);
                int bb = bz >> 2;          // / H
                int h  = bz & 3;
                C[((long)(bb * 512) + m) * 256 + h * 64 + n] = x;
            }
        }
    }
}

// ---------------- K3: Wh2 = multi @ W_out ; t1,t2 ----------------
__global__ void k_gat2_proj(const float* __restrict__ W_out,
                            const float* __restrict__ a_out)
{
    __shared__ float mr[256];
    __shared__ float r1[4], r2[4];
    int row = blockIdx.x;            // b*512 + n
    int t   = threadIdx.x;           // 128
    mr[t]       = g_multi[(long)row * 256 + t];
    mr[t + 128] = g_multi[(long)row * 256 + 128 + t];
    __syncthreads();
    float acc = 0.f;
#pragma unroll 8
    for (int c = 0; c < 256; c++) acc += mr[c] * W_out[c * 128 + t];
    g_Wh2[(long)row * 128 + t] = acc;
    float p1 = acc * a_out[t];
    float p2 = acc * a_out[128 + t];
#pragma unroll
    for (int o = 16; o; o >>= 1) {
        p1 += __shfl_xor_sync(~0u, p1, o);
        p2 += __shfl_xor_sync(~0u, p2, o);
    }
    int w = t >> 5;
    if ((t & 31) == 0) { r1[w] = p1; r2[w] = p2; }
    __syncthreads();
    if (t == 0) {
        g_t1[row] = r1[0] + r1[1] + r1[2] + r1[3];
        g_t2[row] = r2[0] + r2[1] + r2[2] + r2[3];
    }
}

// ---------------- K5: atoms_vector = leaky(elu(hp2) @ Wc + bc) ----------------
__global__ void k_final_atoms(const float* __restrict__ Wc,
                              const float* __restrict__ bc,
                              float* __restrict__ out)
{
    __shared__ float x[128];
    int row = blockIdx.x;            // b*512 + n
    int t   = threadIdx.x;           // 128
    float v = g_hp2[(long)row * 128 + t];
    x[t] = (v > 0.f) ? v : (__expf(v) - 1.f);
    __syncthreads();
    float acc = bc[t];
#pragma unroll 8
    for (int c = 0; c < 128; c++) acc += x[c] * Wc[c * 128 + t];
    acc = (acc >= 0.f) ? acc : 0.2f * acc;
    int b = row >> 9;
    out[((long)row + b * 1024) * 128 + t] = acc;   // b*1536 + n
}

// ---------------- launch ----------------
extern "C" void kernel_launch(void* const* d_in, const int* in_sizes, int n_in,
                              void* d_out, int out_size)
{
    const int*   atoms    = (const int*)  d_in[0];
    const int*   adj      = (const int*)  d_in[1];
    const float* prot     = (const float*)d_in[3];
    const float* emb_atom = (const float*)d_in[5];
    const float* W_gat    = (const float*)d_in[6];
    const float* a_gat    = (const float*)d_in[7];
    const float* W_out    = (const float*)d_in[8];
    const float* a_out    = (const float*)d_in[9];
    const float* Wc       = (const float*)d_in[10];
    const float* bc       = (const float*)d_in[11];
    const float* W1       = (const float*)d_in[12];
    const float* b1       = (const float*)d_in[13];
    const float* W2       = (const float*)d_in[14];
    const float* b2       = (const float*)d_in[15];
    float* out = (float*)d_out;

    void *pWh, *pS1, *pS2, *pAtt1, *pMulti, *pWh2, *pT1, *pT2, *pAtt2, *pHp2, *pHid;
    cudaGetSymbolAddress(&pWh,   g_Wh);
    cudaGetSymbolAddress(&pS1,   g_s1);
    cudaGetSymbolAddress(&pS2,   g_s2);
    cudaGetSymbolAddress(&pAtt1, g_att1);
    cudaGetSymbolAddress(&pMulti,g_multi);
    cudaGetSymbolAddress(&pWh2,  g_Wh2);
    cudaGetSymbolAddress(&pT1,   g_t1);
    cudaGetSymbolAddress(&pT2,   g_t2);
    cudaGetSymbolAddress(&pAtt2, g_att2);
    cudaGetSymbolAddress(&pHp2,  g_hp2);
    cudaGetSymbolAddress(&pHid,  g_hid);

    // GAT layer 1
    k_embed_gat1<<<16 * 512, 256>>>(atoms, emb_atom, W_gat, a_gat);
    k_att_rows<<<16 * 4 * 512, 256>>>((const float*)pS1, (const float*)pS2,
                                      adj, (float*)pAtt1, 4);
    // multi = elu(att1 @ Wh), head-concat layout   [M=512, N=64, K=512] x 64 batches
    sgemm_k<128, 64, 8, 8, 4, 3><<<dim3(1, 4, 64), 256>>>(
        (const float*)pAtt1, (const float*)pWh, nullptr, (float*)pMulti,
        512, 64, 512, (long)512 * 512, (long)512 * 64);

    // GAT layer 2
    k_gat2_proj<<<16 * 512, 128>>>(W_out, a_out);
    k_att_rows<<<16 * 512, 256>>>((const float*)pT1, (const float*)pT2,
                                  adj, (float*)pAtt2, 1);
    // hp2 = att2 @ Wh2   [512,128,512] x 16 batches
    sgemm_k<128, 128, 8, 8, 8, 0><<<dim3(1, 4, 16), 256>>>(
        (const float*)pAtt2, (const float*)pWh2, nullptr, (float*)pHp2,
        512, 128, 512, (long)512 * 512, (long)512 * 128);
    k_final_atoms<<<16 * 512, 128>>>(Wc, bc, out);

    // Protein FC
    // hid = relu(prot @ W1 + b1)  [16384, 512, K=1152]
    sgemm_k<128, 128, 8, 8, 8, 1><<<dim3(4, 128, 1), 256>>>(
        prot, W1, b1, (float*)pHid, 16384, 512, 1152, 0, 0);
    // out_prot = leaky(hid @ W2 + b2)  [16384, 128, K=512], remapped rows
    sgemm_k<128, 128, 8, 8, 8, 2><<<dim3(1, 128, 1), 256>>>(
        (const float*)pHid, W2, b2, out, 16384, 128, 512, 0, 0);
}

// round 2
// speedup vs baseline: 2.3713x; 2.3713x over previous
#include <cuda_runtime.h>

// ---------------- problem constants ----------------
#define Bc    16
#define Nc    512
#define Lc    1024
#define Hc    4
#define COMPc 128
#define GATc  64
#define ESMCc 1152
#define HIDc  512

// ---------------- device scratch ----------------
__device__ float g_Wh  [16u*4*512*64];      // [B,H,N,GAT]
__device__ float g_s1  [16u*4*512];
__device__ float g_s2  [16u*4*512];
__device__ float g_att1[16u*4*512*512];     // [B,H,N,N]
__device__ float g_multi[16u*512*256];      // [B,N,H*GAT]
__device__ float g_Wh2 [16u*512*128];       // [B,N,COMP]
__device__ float g_t1  [16u*512];
__device__ float g_t2  [16u*512];
__device__ float g_att2[16u*512*512];       // [B,N,N]
__device__ float g_hp2 [16u*512*128];
__device__ float g_hid [16u*1024*512];      // [B,L,HID]

// ---------------- PTX helpers ----------------
__device__ __forceinline__ void cp16(float* s, const float* g) {
    unsigned sa = (unsigned)__cvta_generic_to_shared(s);
    asm volatile("cp.async.cg.shared.global [%0], [%1], 16;\n" :: "r"(sa), "l"(g));
}
__device__ __forceinline__ unsigned f2tf(float x) {
    unsigned u; asm("cvt.rna.tf32.f32 %0, %1;" : "=r"(u) : "f"(x)); return u;
}
__device__ __forceinline__ void mma8(float* c, const unsigned* a, const unsigned* b) {
    asm volatile(
        "mma.sync.aligned.m16n8k8.row.col.f32.tf32.tf32.f32 "
        "{%0,%1,%2,%3},{%4,%5,%6,%7},{%8,%9},{%0,%1,%2,%3};"
        : "+f"(c[0]), "+f"(c[1]), "+f"(c[2]), "+f"(c[3])
        : "r"(a[0]), "r"(a[1]), "r"(a[2]), "r"(a[3]), "r"(b[0]), "r"(b[1]));
}

// ---------------- K1: av = emb[atoms]; Wh = av @ W_gat; s1,s2 ----------------
__global__ void k_embed_gat1(const int* __restrict__ atoms,
                             const float* __restrict__ emb_atom,
                             const float* __restrict__ W_gat,
                             const float* __restrict__ a_gat)
{
    __shared__ float av[128];
    __shared__ float r1[8], r2[8];
    int row = blockIdx.x;
    int t   = threadIdx.x;           // 256
    if (t < 128) {
        int atom = atoms[row];
        av[t] = emb_atom[atom * 128 + t];
    }
    __syncthreads();
    int h = t >> 6, f = t & 63;
    const float* Wp = W_gat + (h * 128) * 64 + f;
    float acc = 0.f;
#pragma unroll 8
    for (int c = 0; c < 128; c++) acc += av[c] * Wp[c * 64];
    int b  = row >> 9;
    int n  = row & 511;
    int bh = b * 4 + h;
    g_Wh[((long)bh * 512 + n) * 64 + f] = acc;
    float p1 = acc * a_gat[h * 128 + f];
    float p2 = acc * a_gat[h * 128 + 64 + f];
#pragma unroll
    for (int o = 16; o; o >>= 1) {
        p1 += __shfl_xor_sync(~0u, p1, o);
        p2 += __shfl_xor_sync(~0u, p2, o);
    }
    int w = t >> 5;
    if ((t & 31) == 0) { r1[w] = p1; r2[w] = p2; }
    __syncthreads();
    if ((t & 63) == 0) {
        g_s1[(long)bh * 512 + n] = r1[2 * h] + r1[2 * h + 1];
        g_s2[(long)bh * 512 + n] = r2[2 * h] + r2[2 * h + 1];
    }
}

// ---------------- attention rows: softmax(leaky(s1_i+s2_j) masked) ----------------
__global__ void k_att_rows(const float* __restrict__ s1,
                           const float* __restrict__ s2,
                           const int*   __restrict__ adj,
                           float* __restrict__ att, int Hn)
{
    __shared__ float ebuf[512];
    __shared__ float sred[8];
    __shared__ float bc0, bc1;
    int t   = threadIdx.x;           // 256
    int bhn = blockIdx.x;
    int n   = bhn & 511;
    int bh  = bhn >> 9;
    int b   = bh / Hn;
    float s1v = s1[bh * 512 + n];
    const float* s2r = s2 + bh * 512;
    const int*   ar  = adj + ((long)(b * 512 + n)) * 512;

    float mx = -INFINITY;
#pragma unroll
    for (int jj = 0; jj < 2; jj++) {
        int j = t + jj * 256;
        float x = s1v + s2r[j];
        x = x > 0.f ? x : 0.2f * x;
        float e = (ar[j] > 0) ? x : -9e15f;
        ebuf[j] = e;
        mx = fmaxf(mx, e);
    }
#pragma unroll
    for (int o = 16; o; o >>= 1) mx = fmaxf(mx, __shfl_xor_sync(~0u, mx, o));
    if ((t & 31) == 0) sred[t >> 5] = mx;
    __syncthreads();
    if (t < 8) {
        float v = sred[t];
#pragma unroll
        for (int o = 4; o; o >>= 1) v = fmaxf(v, __shfl_xor_sync(0xffu, v, o));
        if (t == 0) bc0 = v;
    }
    __syncthreads();
    mx = bc0;
    float sum = 0.f;
#pragma unroll
    for (int jj = 0; jj < 2; jj++) {
        int j = t + jj * 256;
        float p = __expf(ebuf[j] - mx);
        ebuf[j] = p;
        sum += p;
    }
    __syncthreads();
#pragma unroll
    for (int o = 16; o; o >>= 1) sum += __shfl_xor_sync(~0u, sum, o);
    if ((t & 31) == 0) sred[t >> 5] = sum;
    __syncthreads();
    if (t < 8) {
        float v = sred[t];
#pragma unroll
        for (int o = 4; o; o >>= 1) v += __shfl_xor_sync(0xffu, v, o);
        if (t == 0) bc1 = v;
    }
    __syncthreads();
    float inv = 1.f / bc1;
    float* arow = att + (long)bhn * 512;
#pragma unroll
    for (int jj = 0; jj < 2; jj++) {
        int j = t + jj * 256;
        arow[j] = ebuf[j] * inv;
    }
}

// ---------------- tf32 tensor-core GEMM, cp.async double-buffered ----------------
// MODE 0: batched plain     C[bz*M*Nn + m*Nn + n]
// MODE 1: relu(x+bias[n])   C[m*Nn+n]
// MODE 2: leaky(x+bias[n]), protein remap out[(b*1536+512+l)*128+n]
// MODE 3: elu(x), head layout C[(b*512+m)*256 + h*64 + n], bz=b*4+h
// MODE 4: plain             C[m*Nn+n]
template<int BM, int BN, int BK, int WM, int WN, int MODE>
__global__ void __launch_bounds__(256)
tf32gemm(const float* __restrict__ A, const float* __restrict__ B,
         const float* __restrict__ bias, float* __restrict__ C,
         int M, int Nn, int K, long sA, long sB)
{
    constexpr int WARPS_M = BM / WM;
    constexpr int WARPS_N = BN / WN;
    static_assert(WARPS_M * WARPS_N == 8, "8 warps");
    constexpr int MT = WM / 16, NT = WN / 8;
    constexpr int AP = BK + 4;
    constexpr int BP = BN + 4;
    __shared__ float As[2][BM * AP];
    __shared__ float Bs[2][BK * BP];

    int tid  = threadIdx.x;
    int lane = tid & 31, warp = tid >> 5;
    int wm = (warp % WARPS_M) * WM;
    int wn = (warp / WARPS_M) * WN;
    int gid = lane >> 2, tig = lane & 3;
    int bz = blockIdx.z;
    const float* Ab = A + (long)bz * sA + (long)(blockIdx.y * BM) * K;
    const float* Bb = B + (long)bz * sB + blockIdx.x * BN;

    float acc[MT][NT][4] = {};

    constexpr int A_IT = BM * BK / 4 / 256;
    constexpr int B_IT = (BK * BN / 4 + 255) / 256;

    int KT = K / BK;
    // stage loader
    auto load_stage = [&](int kt, int st) {
        const float* Ag = Ab + kt * BK;
#pragma unroll
        for (int i = 0; i < A_IT; i++) {
            int c = tid + i * 256;
            int r = c / (BK / 4), kc = c % (BK / 4);
            cp16(&As[st][r * AP + kc * 4], Ag + (long)r * K + kc * 4);
        }
        const float* Bg = Bb + (long)(kt * BK) * Nn;
#pragma unroll
        for (int i = 0; i < B_IT; i++) {
            int c = tid + i * 256;
            if (BK * BN / 4 % 256 == 0 || c < BK * BN / 4) {
                int r = c / (BN / 4), nc = c % (BN / 4);
                cp16(&Bs[st][r * BP + nc * 4], Bg + (long)r * Nn + nc * 4);
            }
        }
        asm volatile("cp.async.commit_group;\n" ::);
    };

    load_stage(0, 0);
    for (int kt = 0; kt < KT; kt++) {
        int st = kt & 1;
        if (kt + 1 < KT) {
            load_stage(kt + 1, st ^ 1);
            asm volatile("cp.async.wait_group 1;\n" ::);
        } else {
            asm volatile("cp.async.wait_group 0;\n" ::);
        }
        __syncthreads();
#pragma unroll
        for (int k8 = 0; k8 < BK / 8; k8++) {
            int kb = k8 * 8;
            unsigned af[MT][4], bf[NT][2];
#pragma unroll
            for (int mt = 0; mt < MT; mt++) {
                int m0 = wm + mt * 16 + gid;
                af[mt][0] = f2tf(As[st][m0 * AP + kb + tig]);
                af[mt][1] = f2tf(As[st][(m0 + 8) * AP + kb + tig]);
                af[mt][2] = f2tf(As[st][m0 * AP + kb + tig + 4]);
                af[mt][3] = f2tf(As[st][(m0 + 8) * AP + kb + tig + 4]);
            }
#pragma unroll
            for (int nt = 0; nt < NT; nt++) {
                int n0 = wn + nt * 8 + gid;
                bf[nt][0] = f2tf(Bs[st][(kb + tig) * BP + n0]);
                bf[nt][1] = f2tf(Bs[st][(kb + tig + 4) * BP + n0]);
            }
#pragma unroll
            for (int mt = 0; mt < MT; mt++)
#pragma unroll
                for (int nt = 0; nt < NT; nt++)
                    mma8(acc[mt][nt], af[mt], bf[nt]);
        }
        __syncthreads();
    }

    // epilogue
#pragma unroll
    for (int mt = 0; mt < MT; mt++) {
#pragma unroll
        for (int nt = 0; nt < NT; nt++) {
#pragma unroll
            for (int h2 = 0; h2 < 2; h2++) {
                int m = blockIdx.y * BM + wm + mt * 16 + gid + h2 * 8;
                int n = blockIdx.x * BN + wn + nt * 8 + tig * 2;
                float v0 = acc[mt][nt][2 * h2];
                float v1 = acc[mt][nt][2 * h2 + 1];
                if (MODE == 0) {
                    long base = (long)bz * M * Nn + (long)m * Nn + n;
                    C[base] = v0; C[base + 1] = v1;
                } else if (MODE == 1) {
                    v0 = fmaxf(v0 + bias[n], 0.f);
                    v1 = fmaxf(v1 + bias[n + 1], 0.f);
                    long base = (long)m * Nn + n;
                    C[base] = v0; C[base + 1] = v1;
                } else if (MODE == 2) {
                    v0 += bias[n]; v1 += bias[n + 1];
                    v0 = (v0 >= 0.f) ? v0 : 0.2f * v0;
                    v1 = (v1 >= 0.f) ? v1 : 0.2f * v1;
                    int bb = m >> 10, l = m & 1023;
                    long base = ((long)(bb * 1536 + 512 + l)) * 128 + n;
                    C[base] = v0; C[base + 1] = v1;
                } else if (MODE == 3) {
                    v0 = (v0 > 0.f) ? v0 : (__expf(v0) - 1.f);
                    v1 = (v1 > 0.f) ? v1 : (__expf(v1) - 1.f);
                    int bb = bz >> 2, h = bz & 3;
                    long base = ((long)(bb * 512) + m) * 256 + h * 64 + n;
                    C[base] = v0; C[base + 1] = v1;
                } else {
                    long base = (long)m * Nn + n;
                    C[base] = v0; C[base + 1] = v1;
                }
            }
        }
    }
}

// ---------------- t1,t2 from Wh2 (row dot with a_out halves) ----------------
__global__ void k_t12(const float* __restrict__ a_out)
{
    __shared__ float r1[4], r2[4];
    int row = blockIdx.x;
    int t   = threadIdx.x;           // 128
    float v  = g_Wh2[(long)row * 128 + t];
    float p1 = v * a_out[t];
    float p2 = v * a_out[128 + t];
#pragma unroll
    for (int o = 16; o; o >>= 1) {
        p1 += __shfl_xor_sync(~0u, p1, o);
        p2 += __shfl_xor_sync(~0u, p2, o);
    }
    int w = t >> 5;
    if ((t & 31) == 0) { r1[w] = p1; r2[w] = p2; }
    __syncthreads();
    if (t == 0) {
        g_t1[row] = r1[0] + r1[1] + r1[2] + r1[3];
        g_t2[row] = r2[0] + r2[1] + r2[2] + r2[3];
    }
}

// ---------------- final: out_atoms = leaky(elu(hp2) @ Wc + bc) ----------------
__global__ void k_final_atoms(const float* __restrict__ Wc,
                              const float* __restrict__ bc,
                              float* __restrict__ out)
{
    __shared__ float x[128];
    int row = blockIdx.x;
    int t   = threadIdx.x;           // 128
    float v = g_hp2[(long)row * 128 + t];
    x[t] = (v > 0.f) ? v : (__expf(v) - 1.f);
    __syncthreads();
    float acc = bc[t];
#pragma unroll 8
    for (int c = 0; c < 128; c++) acc += x[c] * Wc[c * 128 + t];
    acc = (acc >= 0.f) ? acc : 0.2f * acc;
    int b = row >> 9;
    out[((long)row + b * 1024) * 128 + t] = acc;
}

// ---------------- launch ----------------
extern "C" void kernel_launch(void* const* d_in, const int* in_sizes, int n_in,
                              void* d_out, int out_size)
{
    const int*   atoms    = (const int*)  d_in[0];
    const int*   adj      = (const int*)  d_in[1];
    const float* prot     = (const float*)d_in[3];
    const float* emb_atom = (const float*)d_in[5];
    const float* W_gat    = (const float*)d_in[6];
    const float* a_gat    = (const float*)d_in[7];
    const float* W_out    = (const float*)d_in[8];
    const float* a_out    = (const float*)d_in[9];
    const float* Wc       = (const float*)d_in[10];
    const float* bc       = (const float*)d_in[11];
    const float* W1       = (const float*)d_in[12];
    const float* b1       = (const float*)d_in[13];
    const float* W2       = (const float*)d_in[14];
    const float* b2       = (const float*)d_in[15];
    float* out = (float*)d_out;

    void *pWh, *pS1, *pS2, *pAtt1, *pMulti, *pWh2, *pT1, *pT2, *pAtt2, *pHp2, *pHid;
    cudaGetSymbolAddress(&pWh,   g_Wh);
    cudaGetSymbolAddress(&pS1,   g_s1);
    cudaGetSymbolAddress(&pS2,   g_s2);
    cudaGetSymbolAddress(&pAtt1, g_att1);
    cudaGetSymbolAddress(&pMulti,g_multi);
    cudaGetSymbolAddress(&pWh2,  g_Wh2);
    cudaGetSymbolAddress(&pT1,   g_t1);
    cudaGetSymbolAddress(&pT2,   g_t2);
    cudaGetSymbolAddress(&pAtt2, g_att2);
    cudaGetSymbolAddress(&pHp2,  g_hp2);
    cudaGetSymbolAddress(&pHid,  g_hid);

    // ---- GAT layer 1 ----
    k_embed_gat1<<<16 * 512, 256>>>(atoms, emb_atom, W_gat, a_gat);
    k_att_rows<<<16 * 4 * 512, 256>>>((const float*)pS1, (const float*)pS2,
                                      adj, (float*)pAtt1, 4);
    // multi = elu(att1 @ Wh), head concat.  [512 x 64 x 512] x 64 batches
    tf32gemm<128, 64, 16, 64, 16, 3><<<dim3(1, 4, 64), 256>>>(
        (const float*)pAtt1, (const float*)pWh, nullptr, (float*)pMulti,
        512, 64, 512, (long)512 * 512, (long)512 * 64);

    // ---- GAT layer 2 ----
    // Wh2 = multi @ W_out   [8192 x 128 x 256]
    tf32gemm<128, 128, 16, 64, 32, 4><<<dim3(1, 64, 1), 256>>>(
        (const float*)pMulti, W_out, nullptr, (float*)pWh2,
        8192, 128, 256, 0, 0);
    k_t12<<<16 * 512, 128>>>(a_out);
    k_att_rows<<<16 * 512, 256>>>((const float*)pT1, (const float*)pT2,
                                  adj, (float*)pAtt2, 1);
    // hp2 = att2 @ Wh2   [512 x 128 x 512] x 16 batches
    tf32gemm<128, 128, 16, 64, 32, 0><<<dim3(1, 4, 16), 256>>>(
        (const float*)pAtt2, (const float*)pWh2, nullptr, (float*)pHp2,
        512, 128, 512, (long)512 * 512, (long)512 * 128);
    k_final_atoms<<<16 * 512, 128>>>(Wc, bc, out);

    // ---- Protein FC ----
    // hid = relu(prot @ W1 + b1)   [16384 x 512 x 1152]
    tf32gemm<128, 128, 16, 64, 32, 1><<<dim3(4, 128, 1), 256>>>(
        prot, W1, b1, (float*)pHid, 16384, 512, 1152, 0, 0);
    // out_prot = leaky(hid @ W2 + b2)  [16384 x 128 x 512], row remap
    tf32gemm<128, 128, 16, 64, 32, 2><<<dim3(1, 128, 1), 256>>>(
        (const float*)pHid, W2, b2, out, 16384, 128, 512, 0, 0);
}

// round 3
// speedup vs baseline: 2.6508x; 1.1178x over previous
#include <cuda_runtime.h>

// ---------------- device scratch ----------------
__device__ float g_Wh  [16u*4*512*64];      // [B,H,N,GAT]
__device__ float g_s1  [16u*4*512];
__device__ float g_s2  [16u*4*512];
__device__ float g_att1[16u*4*512*512];     // [B,H,N,N]
__device__ float g_multi[16u*512*256];      // [B,N,H*GAT]
__device__ float g_Wh2 [16u*512*128];       // [B,N,COMP]
__device__ float g_t1  [16u*512];
__device__ float g_t2  [16u*512];
__device__ float g_att2[16u*512*512];       // [B,N,N]
__device__ float g_hp2 [16u*512*128];
__device__ float g_hid [16u*1024*512];      // [B,L,HID]

// ---------------- PTX helpers ----------------
__device__ __forceinline__ void cp16(float* s, const float* g) {
    unsigned sa = (unsigned)__cvta_generic_to_shared(s);
    asm volatile("cp.async.cg.shared.global [%0], [%1], 16;\n" :: "r"(sa), "l"(g));
}
__device__ __forceinline__ unsigned f2tf(float x) {
    unsigned u; asm("cvt.rna.tf32.f32 %0, %1;" : "=r"(u) : "f"(x)); return u;
}
__device__ __forceinline__ void mma8(float* c, const unsigned* a, const unsigned* b) {
    asm volatile(
        "mma.sync.aligned.m16n8k8.row.col.f32.tf32.tf32.f32 "
        "{%0,%1,%2,%3},{%4,%5,%6,%7},{%8,%9},{%0,%1,%2,%3};"
        : "+f"(c[0]), "+f"(c[1]), "+f"(c[2]), "+f"(c[3])
        : "r"(a[0]), "r"(a[1]), "r"(a[2]), "r"(a[3]), "r"(b[0]), "r"(b[1]));
}

// ---------------- K1: av = emb[atoms]; Wh = av @ W_gat; s1,s2 ----------------
__global__ void k_embed_gat1(const int* __restrict__ atoms,
                             const float* __restrict__ emb_atom,
                             const float* __restrict__ W_gat,
                             const float* __restrict__ a_gat)
{
    __shared__ float av[128];
    __shared__ float r1[8], r2[8];
    int row = blockIdx.x;
    int t   = threadIdx.x;           // 256
    if (t < 128) {
        int atom = atoms[row];
        av[t] = emb_atom[atom * 128 + t];
    }
    __syncthreads();
    int h = t >> 6, f = t & 63;
    const float* Wp = W_gat + (h * 128) * 64 + f;
    float acc = 0.f;
#pragma unroll 8
    for (int c = 0; c < 128; c++) acc += av[c] * Wp[c * 64];
    int b  = row >> 9;
    int n  = row & 511;
    int bh = b * 4 + h;
    g_Wh[((long)bh * 512 + n) * 64 + f] = acc;
    float p1 = acc * a_gat[h * 128 + f];
    float p2 = acc * a_gat[h * 128 + 64 + f];
#pragma unroll
    for (int o = 16; o; o >>= 1) {
        p1 += __shfl_xor_sync(~0u, p1, o);
        p2 += __shfl_xor_sync(~0u, p2, o);
    }
    int w = t >> 5;
    if ((t & 31) == 0) { r1[w] = p1; r2[w] = p2; }
    __syncthreads();
    if ((t & 63) == 0) {
        g_s1[(long)bh * 512 + n] = r1[2 * h] + r1[2 * h + 1];
        g_s2[(long)bh * 512 + n] = r2[2 * h] + r2[2 * h + 1];
    }
}

// ---------------- fused attention rows, all heads per (b,n) block --------------
// softmax(leaky(s1_i+s2_j)) with mask; no max-pass (scores ~1e-2, exp safe;
// masked lanes contribute exactly 0, identical to ref softmax with -9e15).
__global__ void k_att_rows(const float* __restrict__ s1,
                           const float* __restrict__ s2,
                           const int*   __restrict__ adj,
                           float* __restrict__ att, int heads)
{
    __shared__ float sred[8];
    __shared__ float sinv;
    int t  = threadIdx.x;            // 256
    int bn = blockIdx.x;             // b*512 + n
    int n  = bn & 511;
    int b  = bn >> 9;
    const int* ar = adj + (long)bn * 512;
    int a0 = ar[t], a1 = ar[t + 256];

    for (int h = 0; h < heads; h++) {
        int bh = b * heads + h;
        float s1v = s1[bh * 512 + n];
        const float* s2r = s2 + bh * 512;
        float x0 = s1v + s2r[t];
        float x1 = s1v + s2r[t + 256];
        x0 = x0 > 0.f ? x0 : 0.2f * x0;
        x1 = x1 > 0.f ? x1 : 0.2f * x1;
        float p0 = (a0 > 0) ? __expf(x0) : 0.f;
        float p1 = (a1 > 0) ? __expf(x1) : 0.f;
        float sum = p0 + p1;
#pragma unroll
        for (int o = 16; o; o >>= 1) sum += __shfl_xor_sync(~0u, sum, o);
        if ((t & 31) == 0) sred[t >> 5] = sum;
        __syncthreads();
        if (t < 8) {
            float v = sred[t];
#pragma unroll
            for (int o = 4; o; o >>= 1) v += __shfl_xor_sync(0xffu, v, o);
            if (t == 0) sinv = 1.f / v;
        }
        __syncthreads();
        float inv = sinv;
        float* arow = att + ((long)bh * 512 + n) * 512;
        arow[t]       = p0 * inv;
        arow[t + 256] = p1 * inv;
        if (h + 1 < heads) __syncthreads();
    }
}

// ---------------- tf32 tensor-core GEMM, multi-stage cp.async ----------------
// MODE 0: batched plain      C[bz*M*Nn + m*Nn + n]
// MODE 1: relu(x+bias[n])    C[m*Nn+n]
// MODE 2: leaky(x+bias[n]), protein remap out[(b*1536+512+l)*128+n]
// MODE 3: elu(x), head layout C[(b*512+m)*256 + h*64 + n], bz=b*4+h
// MODE 4: plain              C[m*Nn+n]
template<int BM, int BN, int BK, int WM, int WN, int MODE, int STAGES>
__global__ void __launch_bounds__(256)
tf32gemm(const float* __restrict__ A, const float* __restrict__ B,
         const float* __restrict__ bias, float* __restrict__ C,
         int M, int Nn, int K, long sA, long sB)
{
    constexpr int WARPS_M = BM / WM;
    constexpr int WARPS_N = BN / WN;
    static_assert(WARPS_M * WARPS_N == 8, "8 warps");
    constexpr int MT = WM / 16, NT = WN / 8;
    constexpr int AP = BK + 4;
    constexpr int BP = BN + 4;
    extern __shared__ float dyn[];
    float* Asm = dyn;                          // STAGES * BM * AP
    float* Bsm = dyn + STAGES * BM * AP;       // STAGES * BK * BP

    int tid  = threadIdx.x;
    int lane = tid & 31, warp = tid >> 5;
    int wm = (warp % WARPS_M) * WM;
    int wn = (warp / WARPS_M) * WN;
    int gid = lane >> 2, tig = lane & 3;
    int bz = blockIdx.z;
    const float* Ab = A + (long)bz * sA + (long)(blockIdx.y * BM) * K;
    const float* Bb = B + (long)bz * sB + blockIdx.x * BN;

    float acc[MT][NT][4] = {};

    constexpr int A_IT = BM * BK / 4 / 256;
    constexpr int B_IT = (BK * BN / 4 + 255) / 256;

    int KT = K / BK;
    auto load_stage = [&](int kt, int st) {
        float* As = Asm + st * BM * AP;
        float* Bs = Bsm + st * BK * BP;
        const float* Ag = Ab + kt * BK;
#pragma unroll
        for (int i = 0; i < A_IT; i++) {
            int c = tid + i * 256;
            int r = c / (BK / 4), kc = c % (BK / 4);
            cp16(&As[r * AP + kc * 4], Ag + (long)r * K + kc * 4);
        }
        const float* Bg = Bb + (long)(kt * BK) * Nn;
#pragma unroll
        for (int i = 0; i < B_IT; i++) {
            int c = tid + i * 256;
            if (BK * BN / 4 % 256 == 0 || c < BK * BN / 4) {
                int r = c / (BN / 4), nc = c % (BN / 4);
                cp16(&Bs[r * BP + nc * 4], Bg + (long)r * Nn + nc * 4);
            }
        }
        asm volatile("cp.async.commit_group;\n" ::);
    };

#pragma unroll
    for (int s = 0; s < STAGES - 1; s++)
        if (s < KT) load_stage(s, s);

    for (int kt = 0; kt < KT; kt++) {
        int st = kt % STAGES;
        asm volatile("cp.async.wait_group %0;\n" :: "n"(STAGES - 2));
        __syncthreads();
        int pf = kt + STAGES - 1;
        if (pf < KT) load_stage(pf, pf % STAGES);

        float* As = Asm + st * BM * AP;
        float* Bs = Bsm + st * BK * BP;
#pragma unroll
        for (int k8 = 0; k8 < BK / 8; k8++) {
            int kb = k8 * 8;
            unsigned af[MT][4], bf[NT][2];
#pragma unroll
            for (int mt = 0; mt < MT; mt++) {
                int m0 = wm + mt * 16 + gid;
                af[mt][0] = f2tf(As[m0 * AP + kb + tig]);
                af[mt][1] = f2tf(As[(m0 + 8) * AP + kb + tig]);
                af[mt][2] = f2tf(As[m0 * AP + kb + tig + 4]);
                af[mt][3] = f2tf(As[(m0 + 8) * AP + kb + tig + 4]);
            }
#pragma unroll
            for (int nt = 0; nt < NT; nt++) {
                int n0 = wn + nt * 8 + gid;
                bf[nt][0] = f2tf(Bs[(kb + tig) * BP + n0]);
                bf[nt][1] = f2tf(Bs[(kb + tig + 4) * BP + n0]);
            }
#pragma unroll
            for (int mt = 0; mt < MT; mt++)
#pragma unroll
                for (int nt = 0; nt < NT; nt++)
                    mma8(acc[mt][nt], af[mt], bf[nt]);
        }
        __syncthreads();
    }

#pragma unroll
    for (int mt = 0; mt < MT; mt++) {
#pragma unroll
        for (int nt = 0; nt < NT; nt++) {
#pragma unroll
            for (int h2 = 0; h2 < 2; h2++) {
                int m = blockIdx.y * BM + wm + mt * 16 + gid + h2 * 8;
                int n = blockIdx.x * BN + wn + nt * 8 + tig * 2;
                float v0 = acc[mt][nt][2 * h2];
                float v1 = acc[mt][nt][2 * h2 + 1];
                if (MODE == 0) {
                    long base = (long)bz * M * Nn + (long)m * Nn + n;
                    C[base] = v0; C[base + 1] = v1;
                } else if (MODE == 1) {
                    v0 = fmaxf(v0 + bias[n], 0.f);
                    v1 = fmaxf(v1 + bias[n + 1], 0.f);
                    long base = (long)m * Nn + n;
                    C[base] = v0; C[base + 1] = v1;
                } else if (MODE == 2) {
                    v0 += bias[n]; v1 += bias[n + 1];
                    v0 = (v0 >= 0.f) ? v0 : 0.2f * v0;
                    v1 = (v1 >= 0.f) ? v1 : 0.2f * v1;
                    int bb = m >> 10, l = m & 1023;
                    long base = ((long)(bb * 1536 + 512 + l)) * 128 + n;
                    C[base] = v0; C[base + 1] = v1;
                } else if (MODE == 3) {
                    v0 = (v0 > 0.f) ? v0 : (__expf(v0) - 1.f);
                    v1 = (v1 > 0.f) ? v1 : (__expf(v1) - 1.f);
                    int bb = bz >> 2, h = bz & 3;
                    long base = ((long)(bb * 512) + m) * 256 + h * 64 + n;
                    C[base] = v0; C[base + 1] = v1;
                } else {
                    long base = (long)m * Nn + n;
                    C[base] = v0; C[base + 1] = v1;
                }
            }
        }
    }
}

// ---------------- t1,t2 from Wh2 ----------------
__global__ void k_t12(const float* __restrict__ a_out)
{
    __shared__ float r1[4], r2[4];
    int row = blockIdx.x;
    int t   = threadIdx.x;           // 128
    float v  = g_Wh2[(long)row * 128 + t];
    float p1 = v * a_out[t];
    float p2 = v * a_out[128 + t];
#pragma unroll
    for (int o = 16; o; o >>= 1) {
        p1 += __shfl_xor_sync(~0u, p1, o);
        p2 += __shfl_xor_sync(~0u, p2, o);
    }
    int w = t >> 5;
    if ((t & 31) == 0) { r1[w] = p1; r2[w] = p2; }
    __syncthreads();
    if (t == 0) {
        g_t1[row] = r1[0] + r1[1] + r1[2] + r1[3];
        g_t2[row] = r2[0] + r2[1] + r2[2] + r2[3];
    }
}

// ---------------- final: out_atoms = leaky(elu(hp2) @ Wc + bc) ----------------
__global__ void k_final_atoms(const float* __restrict__ Wc,
                              const float* __restrict__ bc,
                              float* __restrict__ out)
{
    __shared__ float x[128];
    int row = blockIdx.x;
    int t   = threadIdx.x;           // 128
    float v = g_hp2[(long)row * 128 + t];
    x[t] = (v > 0.f) ? v : (__expf(v) - 1.f);
    __syncthreads();
    float acc = bc[t];
#pragma unroll 8
    for (int c = 0; c < 128; c++) acc += x[c] * Wc[c * 128 + t];
    acc = (acc >= 0.f) ? acc : 0.2f * acc;
    int b = row >> 9;
    out[((long)row + b * 1024) * 128 + t] = acc;
}

// ---------------- launch ----------------
static inline int gemm_smem(int BM, int BN, int BK, int ST) {
    return ST * (BM * (BK + 4) + BK * (BN + 4)) * (int)sizeof(float);
}

extern "C" void kernel_launch(void* const* d_in, const int* in_sizes, int n_in,
                              void* d_out, int out_size)
{
    const int*   atoms    = (const int*)  d_in[0];
    const int*   adj      = (const int*)  d_in[1];
    const float* prot     = (const float*)d_in[3];
    const float* emb_atom = (const float*)d_in[5];
    const float* W_gat    = (const float*)d_in[6];
    const float* a_gat    = (const float*)d_in[7];
    const float* W_out    = (const float*)d_in[8];
    const float* a_out    = (const float*)d_in[9];
    const float* Wc       = (const float*)d_in[10];
    const float* bc       = (const float*)d_in[11];
    const float* W1       = (const float*)d_in[12];
    const float* b1       = (const float*)d_in[13];
    const float* W2       = (const float*)d_in[14];
    const float* b2       = (const float*)d_in[15];
    float* out = (float*)d_out;

    void *pWh, *pS1, *pS2, *pAtt1, *pMulti, *pWh2, *pT1, *pT2, *pAtt2, *pHp2, *pHid;
    cudaGetSymbolAddress(&pWh,   g_Wh);
    cudaGetSymbolAddress(&pS1,   g_s1);
    cudaGetSymbolAddress(&pS2,   g_s2);
    cudaGetSymbolAddress(&pAtt1, g_att1);
    cudaGetSymbolAddress(&pMulti,g_multi);
    cudaGetSymbolAddress(&pWh2,  g_Wh2);
    cudaGetSymbolAddress(&pT1,   g_t1);
    cudaGetSymbolAddress(&pT2,   g_t2);
    cudaGetSymbolAddress(&pAtt2, g_att2);
    cudaGetSymbolAddress(&pHp2,  g_hp2);
    cudaGetSymbolAddress(&pHid,  g_hid);

    // one-time host resources (streams/events for graph fork-join)
    static cudaStream_t sB = nullptr;
    static cudaEvent_t evFork = nullptr, evJoin = nullptr;
    if (!sB) {
        cudaStreamCreateWithFlags(&sB, cudaStreamNonBlocking);
        cudaEventCreateWithFlags(&evFork, cudaEventDisableTiming);
        cudaEventCreateWithFlags(&evJoin, cudaEventDisableTiming);
        // opt-in >48KB dynamic smem for the big-tile GEMMs
        cudaFuncSetAttribute(tf32gemm<128,128,16,64,32,1,3>,
                             cudaFuncAttributeMaxDynamicSharedMemorySize,
                             gemm_smem(128,128,16,3));
        cudaFuncSetAttribute(tf32gemm<128,64,16,64,16,3,3>,
                             cudaFuncAttributeMaxDynamicSharedMemorySize,
                             gemm_smem(128,64,16,3));
        cudaFuncSetAttribute(tf32gemm<64,128,16,32,32,4,3>,
                             cudaFuncAttributeMaxDynamicSharedMemorySize,
                             gemm_smem(64,128,16,3));
        cudaFuncSetAttribute(tf32gemm<64,128,16,32,32,0,3>,
                             cudaFuncAttributeMaxDynamicSharedMemorySize,
                             gemm_smem(64,128,16,3));
        cudaFuncSetAttribute(tf32gemm<64,128,16,32,32,2,3>,
                             cudaFuncAttributeMaxDynamicSharedMemorySize,
                             gemm_smem(64,128,16,3));
    }

    // ---- fork: protein FC chain on stream B ----
    cudaEventRecord(evFork, 0);
    cudaStreamWaitEvent(sB, evFork, 0);

    // hid = relu(prot @ W1 + b1)   [16384 x 512 x 1152]
    tf32gemm<128,128,16,64,32,1,3><<<dim3(4,128,1), 256, gemm_smem(128,128,16,3), sB>>>(
        prot, W1, b1, (float*)pHid, 16384, 512, 1152, 0, 0);
    // out_prot = leaky(hid @ W2 + b2)  [16384 x 128 x 512], row remap
    tf32gemm<64,128,16,32,32,2,3><<<dim3(1,256,1), 256, gemm_smem(64,128,16,3), sB>>>(
        (const float*)pHid, W2, b2, out, 16384, 128, 512, 0, 0);
    cudaEventRecord(evJoin, sB);

    // ---- GAT chain on origin stream ----
    k_embed_gat1<<<16 * 512, 256>>>(atoms, emb_atom, W_gat, a_gat);
    k_att_rows<<<16 * 512, 256>>>((const float*)pS1, (const float*)pS2,
                                  adj, (float*)pAtt1, 4);
    // multi = elu(att1 @ Wh)   [512 x 64 x 512] x 64 batches
    tf32gemm<128,64,16,64,16,3,3><<<dim3(1,4,64), 256, gemm_smem(128,64,16,3)>>>(
        (const float*)pAtt1, (const float*)pWh, nullptr, (float*)pMulti,
        512, 64, 512, (long)512 * 512, (long)512 * 64);
    // Wh2 = multi @ W_out   [8192 x 128 x 256]
    tf32gemm<64,128,16,32,32,4,3><<<dim3(1,128,1), 256, gemm_smem(64,128,16,3)>>>(
        (const float*)pMulti, W_out, nullptr, (float*)pWh2, 8192, 128, 256, 0, 0);
    k_t12<<<16 * 512, 128>>>(a_out);
    k_att_rows<<<16 * 512, 256>>>((const float*)pT1, (const float*)pT2,
                                  adj, (float*)pAtt2, 1);
    // hp2 = att2 @ Wh2   [512 x 128 x 512] x 16 batches
    tf32gemm<64,128,16,32,32,0,3><<<dim3(1,8,16), 256, gemm_smem(64,128,16,3)>>>(
        (const float*)pAtt2, (const float*)pWh2, nullptr, (float*)pHp2,
        512, 128, 512, (long)512 * 512, (long)512 * 128);
    k_final_atoms<<<16 * 512, 128>>>(Wc, bc, out);

    // ---- join ----
    cudaStreamWaitEvent(0, evJoin, 0);
}

// round 7
// speedup vs baseline: 2.8446x; 1.0731x over previous
#include <cuda_runtime.h>

// ---------------- device scratch ----------------
__device__ float g_protR[16u*1024*1152];    // tf32-rounded prot
__device__ float g_W1R [1152*512];
__device__ float g_W2R [512*128];
__device__ float g_WoutR[256*128];
__device__ float g_Wh  [16u*4*512*64];      // [B,H,N,GAT] (tf32-rounded)
__device__ float g_s1  [16u*4*512];
__device__ float g_s2  [16u*4*512];
__device__ float g_att1[16u*4*512*512];     // [B,H,N,N] (tf32-rounded)
__device__ float g_multi[16u*512*256];      // [B,N,H*GAT] (tf32-rounded)
__device__ float g_Wh2 [16u*512*128];       // (tf32-rounded)
__device__ float g_t1  [16u*512];
__device__ float g_t2  [16u*512];
__device__ float g_att2[16u*512*512];       // (tf32-rounded)
__device__ float g_hp2 [16u*512*128];
__device__ float g_hid [16u*1024*512];      // (tf32-rounded)

// ---------------- PTX helpers ----------------
__device__ __forceinline__ void cp16(float* s, const float* g) {
    unsigned sa = (unsigned)__cvta_generic_to_shared(s);
    asm volatile("cp.async.cg.shared.global [%0], [%1], 16;\n" :: "r"(sa), "l"(g));
}
__device__ __forceinline__ float rnd(float x) {   // round to tf32, keep fp32 layout
    unsigned u; asm("cvt.rna.tf32.f32 %0, %1;" : "=r"(u) : "f"(x));
    return __uint_as_float(u);
}
__device__ __forceinline__ void mma8(float* c, const unsigned* a, const unsigned* b) {
    asm volatile(
        "mma.sync.aligned.m16n8k8.row.col.f32.tf32.tf32.f32 "
        "{%0,%1,%2,%3},{%4,%5,%6,%7},{%8,%9},{%0,%1,%2,%3};"
        : "+f"(c[0]), "+f"(c[1]), "+f"(c[2]), "+f"(c[3])
        : "r"(a[0]), "r"(a[1]), "r"(a[2]), "r"(a[3]), "r"(b[0]), "r"(b[1]));
}

// ---------------- elementwise tf32 rounding pass ----------------
__global__ void k_round(const float* __restrict__ src, float* __restrict__ dst, int n4)
{
    int i = blockIdx.x * blockDim.x + threadIdx.x;
    int stride = gridDim.x * blockDim.x;
    for (; i < n4; i += stride) {
        float4 v = ((const float4*)src)[i];
        v.x = rnd(v.x); v.y = rnd(v.y); v.z = rnd(v.z); v.w = rnd(v.w);
        ((float4*)dst)[i] = v;
    }
}

// ---------------- K1: av = emb[atoms]; Wh = av @ W_gat; s1,s2 ----------------
__global__ void k_embed_gat1(const int* __restrict__ atoms,
                             const float* __restrict__ emb_atom,
                             const float* __restrict__ W_gat,
                             const float* __restrict__ a_gat)
{
    __shared__ float av[128];
    __shared__ float r1[8], r2[8];
    int row = blockIdx.x;
    int t   = threadIdx.x;           // 256
    if (t < 128) {
        int atom = atoms[row];
        av[t] = emb_atom[atom * 128 + t];
    }
    __syncthreads();
    int h = t >> 6, f = t & 63;
    const float* Wp = W_gat + (h * 128) * 64 + f;
    float acc = 0.f;
#pragma unroll 8
    for (int c = 0; c < 128; c++) acc += av[c] * Wp[c * 64];
    int b  = row >> 9;
    int n  = row & 511;
    int bh = b * 4 + h;
    g_Wh[((long)bh * 512 + n) * 64 + f] = rnd(acc);
    float p1 = acc * a_gat[h * 128 + f];
    float p2 = acc * a_gat[h * 128 + 64 + f];
#pragma unroll
    for (int o = 16; o; o >>= 1) {
        p1 += __shfl_xor_sync(~0u, p1, o);
        p2 += __shfl_xor_sync(~0u, p2, o);
    }
    int w = t >> 5;
    if ((t & 31) == 0) { r1[w] = p1; r2[w] = p2; }
    __syncthreads();
    if ((t & 63) == 0) {
        g_s1[(long)bh * 512 + n] = r1[2 * h] + r1[2 * h + 1];
        g_s2[(long)bh * 512 + n] = r2[2 * h] + r2[2 * h + 1];
    }
}

// ---------------- fused attention rows, all heads per (b,n) block --------------
__global__ void k_att_rows(const float* __restrict__ s1,
                           const float* __restrict__ s2,
                           const int*   __restrict__ adj,
                           float* __restrict__ att, int heads)
{
    __shared__ float sred[8];
    __shared__ float sinv;
    int t  = threadIdx.x;            // 256
    int bn = blockIdx.x;             // b*512 + n
    int n  = bn & 511;
    int b  = bn >> 9;
    const int* ar = adj + (long)bn * 512;
    int a0 = ar[t], a1 = ar[t + 256];

    for (int h = 0; h < heads; h++) {
        int bh = b * heads + h;
        float s1v = s1[bh * 512 + n];
        const float* s2r = s2 + bh * 512;
        float x0 = s1v + s2r[t];
        float x1 = s1v + s2r[t + 256];
        x0 = x0 > 0.f ? x0 : 0.2f * x0;
        x1 = x1 > 0.f ? x1 : 0.2f * x1;
        float p0 = (a0 > 0) ? __expf(x0) : 0.f;
        float p1 = (a1 > 0) ? __expf(x1) : 0.f;
        float sum = p0 + p1;
#pragma unroll
        for (int o = 16; o; o >>= 1) sum += __shfl_xor_sync(~0u, sum, o);
        if ((t & 31) == 0) sred[t >> 5] = sum;
        __syncthreads();
        if (t < 8) {
            float v = sred[t];
#pragma unroll
            for (int o = 4; o; o >>= 1) v += __shfl_xor_sync(0xffu, v, o);
            if (t == 0) sinv = 1.f / v;
        }
        __syncthreads();
        float inv = sinv;
        float* arow = att + ((long)bh * 512 + n) * 512;
        arow[t]       = rnd(p0 * inv);
        arow[t + 256] = rnd(p1 * inv);
        if (h + 1 < heads) __syncthreads();
    }
}

// ---------------- tf32 tensor-core GEMM, multi-stage cp.async ----------------
// All operands are pre-rounded tf32 bit-patterns; mainloop is pure LDS+MMA.
// MODE 0: batched plain      C[bz*M*Nn + m*Nn + n]
// MODE 1: relu(x+bias[n]), rnd   C[m*Nn+n]
// MODE 2: leaky(x+bias[n]), protein remap out[(b*1536+512+l)*128+n]  (fp32)
// MODE 3: elu(x), rnd, head layout C[(b*512+m)*256 + h*64 + n], bz=b*4+h
// MODE 4: plain, rnd         C[m*Nn+n]
template<int BM, int BN, int BK, int WM, int WN, int MODE, int STAGES>
__global__ void __launch_bounds__(256)
tf32gemm(const float* __restrict__ A, const float* __restrict__ B,
         const float* __restrict__ bias, float* __restrict__ C,
         int M, int Nn, int K, long sA, long sB)
{
    constexpr int WARPS_M = BM / WM;
    constexpr int WARPS_N = BN / WN;
    static_assert(WARPS_M * WARPS_N == 8, "8 warps");
    constexpr int MT = WM / 16, NT = WN / 8;
    constexpr int AP = BK + 4;
    constexpr int BP = BN + 8;               // conflict-free B fragment loads
    extern __shared__ float dyn[];
    float* Asm = dyn;                         // STAGES * BM * AP
    float* Bsm = dyn + STAGES * BM * AP;      // STAGES * BK * BP

    int tid  = threadIdx.x;
    int lane = tid & 31, warp = tid >> 5;
    int wm = (warp % WARPS_M) * WM;
    int wn = (warp / WARPS_M) * WN;
    int gid = lane >> 2, tig = lane & 3;
    int bz = blockIdx.z;
    const float* Ab = A + (long)bz * sA + (long)(blockIdx.y * BM) * K;
    const float* Bb = B + (long)bz * sB + blockIdx.x * BN;

    float acc[MT][NT][4] = {};

    constexpr int A_IT = BM * BK / 4 / 256;
    constexpr int B_IT = (BK * BN / 4 + 255) / 256;

    int KT = K / BK;
    auto load_stage = [&](int kt, int st) {
        float* As = Asm + st * BM * AP;
        float* Bs = Bsm + st * BK * BP;
        const float* Ag = Ab + kt * BK;
#pragma unroll
        for (int i = 0; i < A_IT; i++) {
            int c = tid + i * 256;
            int r = c / (BK / 4), kc = c % (BK / 4);
            cp16(&As[r * AP + kc * 4], Ag + (long)r * K + kc * 4);
        }
        const float* Bg = Bb + (long)(kt * BK) * Nn;
#pragma unroll
        for (int i = 0; i < B_IT; i++) {
            int c = tid + i * 256;
            if (BK * BN / 4 % 256 == 0 || c < BK * BN / 4) {
                int r = c / (BN / 4), nc = c % (BN / 4);
                cp16(&Bs[r * BP + nc * 4], Bg + (long)r * Nn + nc * 4);
            }
        }
        asm volatile("cp.async.commit_group;\n" ::);
    };

#pragma unroll
    for (int s = 0; s < STAGES - 1; s++)
        if (s < KT) load_stage(s, s);

    for (int kt = 0; kt < KT; kt++) {
        int st = kt % STAGES;
        asm volatile("cp.async.wait_group %0;\n" :: "n"(STAGES - 2));
        __syncthreads();
        int pf = kt + STAGES - 1;
        if (pf < KT) load_stage(pf, pf % STAGES);

        float* As = Asm + st * BM * AP;
        float* Bs = Bsm + st * BK * BP;
#pragma unroll
        for (int k8 = 0; k8 < BK / 8; k8++) {
            int kb = k8 * 8;
            unsigned af[MT][4], bf[NT][2];
#pragma unroll
            for (int mt = 0; mt < MT; mt++) {
                int m0 = wm + mt * 16 + gid;
                af[mt][0] = __float_as_uint(As[m0 * AP + kb + tig]);
                af[mt][1] = __float_as_uint(As[(m0 + 8) * AP + kb + tig]);
                af[mt][2] = __float_as_uint(As[m0 * AP + kb + tig + 4]);
                af[mt][3] = __float_as_uint(As[(m0 + 8) * AP + kb + tig + 4]);
            }
#pragma unroll
            for (int nt = 0; nt < NT; nt++) {
                int n0 = wn + nt * 8 + gid;
                bf[nt][0] = __float_as_uint(Bs[(kb + tig) * BP + n0]);
                bf[nt][1] = __float_as_uint(Bs[(kb + tig + 4) * BP + n0]);
            }
#pragma unroll
            for (int mt = 0; mt < MT; mt++)
#pragma unroll
                for (int nt = 0; nt < NT; nt++)
                    mma8(acc[mt][nt], af[mt], bf[nt]);
        }
        __syncthreads();
    }

#pragma unroll
    for (int mt = 0; mt < MT; mt++) {
#pragma unroll
        for (int nt = 0; nt < NT; nt++) {
#pragma unroll
            for (int h2 = 0; h2 < 2; h2++) {
                int m = blockIdx.y * BM + wm + mt * 16 + gid + h2 * 8;
                int n = blockIdx.x * BN + wn + nt * 8 + tig * 2;
                float v0 = acc[mt][nt][2 * h2];
                float v1 = acc[mt][nt][2 * h2 + 1];
                if (MODE == 0) {
                    long base = (long)bz * M * Nn + (long)m * Nn + n;
                    C[base] = v0; C[base + 1] = v1;
                } else if (MODE == 1) {
                    v0 = fmaxf(v0 + bias[n], 0.f);
                    v1 = fmaxf(v1 + bias[n + 1], 0.f);
                    long base = (long)m * Nn + n;
                    C[base] = rnd(v0); C[base + 1] = rnd(v1);
                } else if (MODE == 2) {
                    v0 += bias[n]; v1 += bias[n + 1];
                    v0 = (v0 >= 0.f) ? v0 : 0.2f * v0;
                    v1 = (v1 >= 0.f) ? v1 : 0.2f * v1;
                    int bb = m >> 10, l = m & 1023;
                    long base = ((long)(bb * 1536 + 512 + l)) * 128 + n;
                    C[base] = v0; C[base + 1] = v1;
                } else if (MODE == 3) {
                    v0 = (v0 > 0.f) ? v0 : (__expf(v0) - 1.f);
                    v1 = (v1 > 0.f) ? v1 : (__expf(v1) - 1.f);
                    int bb = bz >> 2, h = bz & 3;
                    long base = ((long)(bb * 512) + m) * 256 + h * 64 + n;
                    C[base] = rnd(v0); C[base + 1] = rnd(v1);
                } else {
                    long base = (long)m * Nn + n;
                    C[base] = rnd(v0); C[base + 1] = rnd(v1);
                }
            }
        }
    }
}

// ---------------- t1,t2 from Wh2 ----------------
__global__ void k_t12(const float* __restrict__ a_out)
{
    __shared__ float r1[4], r2[4];
    int row = blockIdx.x;
    int t   = threadIdx.x;           // 128
    float v  = g_Wh2[(long)row * 128 + t];
    float p1 = v * a_out[t];
    float p2 = v * a_out[128 + t];
#pragma unroll
    for (int o = 16; o; o >>= 1) {
        p1 += __shfl_xor_sync(~0u, p1, o);
        p2 += __shfl_xor_sync(~0u, p2, o);
    }
    int w = t >> 5;
    if ((t & 31) == 0) { r1[w] = p1; r2[w] = p2; }
    __syncthreads();
    if (t == 0) {
        g_t1[row] = r1[0] + r1[1] + r1[2] + r1[3];
        g_t2[row] = r2[0] + r2[1] + r2[2] + r2[3];
    }
}

// ---------------- final: out_atoms = leaky(elu(hp2) @ Wc + bc) ----------------
__global__ void k_final_atoms(const float* __restrict__ Wc,
                              const float* __restrict__ bc,
                              float* __restrict__ out)
{
    __shared__ float x[128];
    int row = blockIdx.x;
    int t   = threadIdx.x;           // 128
    float v = g_hp2[(long)row * 128 + t];
    x[t] = (v > 0.f) ? v : (__expf(v) - 1.f);
    __syncthreads();
    float acc = bc[t];
#pragma unroll 8
    for (int c = 0; c < 128; c++) acc += x[c] * Wc[c * 128 + t];
    acc = (acc >= 0.f) ? acc : 0.2f * acc;
    int b = row >> 9;
    out[((long)row + b * 1024) * 128 + t] = acc;
}

// ---------------- launch ----------------
static inline int gemm_smem(int BM, int BN, int BK, int ST) {
    return ST * (BM * (BK + 4) + BK * (BN + 8)) * (int)sizeof(float);
}

extern "C" void kernel_launch(void* const* d_in, const int* in_sizes, int n_in,
                              void* d_out, int out_size)
{
    const int*   atoms    = (const int*)  d_in[0];
    const int*   adj      = (const int*)  d_in[1];
    const float* prot     = (const float*)d_in[3];
    const float* emb_atom = (const float*)d_in[5];
    const float* W_gat    = (const float*)d_in[6];
    const float* a_gat    = (const float*)d_in[7];
    const float* W_out    = (const float*)d_in[8];
    const float* a_out    = (const float*)d_in[9];
    const float* Wc       = (const float*)d_in[10];
    const float* bc       = (const float*)d_in[11];
    const float* W1       = (const float*)d_in[12];
    const float* b1       = (const float*)d_in[13];
    const float* W2       = (const float*)d_in[14];
    const float* b2       = (const float*)d_in[15];
    float* out = (float*)d_out;

    void *pProtR, *pW1R, *pW2R, *pWoutR;
    void *pWh, *pS1, *pS2, *pAtt1, *pMulti, *pWh2, *pT1, *pT2, *pAtt2, *pHp2, *pHid;
    cudaGetSymbolAddress(&pProtR, g_protR);
    cudaGetSymbolAddress(&pW1R,  g_W1R);
    cudaGetSymbolAddress(&pW2R,  g_W2R);
    cudaGetSymbolAddress(&pWoutR,g_WoutR);
    cudaGetSymbolAddress(&pWh,   g_Wh);
    cudaGetSymbolAddress(&pS1,   g_s1);
    cudaGetSymbolAddress(&pS2,   g_s2);
    cudaGetSymbolAddress(&pAtt1, g_att1);
    cudaGetSymbolAddress(&pMulti,g_multi);
    cudaGetSymbolAddress(&pWh2,  g_Wh2);
    cudaGetSymbolAddress(&pT1,   g_t1);
    cudaGetSymbolAddress(&pT2,   g_t2);
    cudaGetSymbolAddress(&pAtt2, g_att2);
    cudaGetSymbolAddress(&pHp2,  g_hp2);
    cudaGetSymbolAddress(&pHid,  g_hid);

    static cudaStream_t sB = nullptr;
    static cudaEvent_t evFork = nullptr, evJoin = nullptr;
    if (!sB) {
        cudaStreamCreateWithFlags(&sB, cudaStreamNonBlocking);
        cudaEventCreateWithFlags(&evFork, cudaEventDisableTiming);
        cudaEventCreateWithFlags(&evJoin, cudaEventDisableTiming);
        cudaFuncSetAttribute(tf32gemm<128,128,16,64,32,1,3>,
                             cudaFuncAttributeMaxDynamicSharedMemorySize,
                             gemm_smem(128,128,16,3));
        cudaFuncSetAttribute(tf32gemm<128,64,16,64,16,3,3>,
                             cudaFuncAttributeMaxDynamicSharedMemorySize,
                             gemm_smem(128,64,16,3));
        cudaFuncSetAttribute(tf32gemm<64,128,16,32,32,4,3>,
                             cudaFuncAttributeMaxDynamicSharedMemorySize,
                             gemm_smem(64,128,16,3));
        cudaFuncSetAttribute(tf32gemm<64,128,16,32,32,0,3>,
                             cudaFuncAttributeMaxDynamicSharedMemorySize,
                             gemm_smem(64,128,16,3));
        cudaFuncSetAttribute(tf32gemm<64,128,16,32,32,2,3>,
                             cudaFuncAttributeMaxDynamicSharedMemorySize,
                             gemm_smem(64,128,16,3));
    }

    // ---- fork: protein FC chain on stream B ----
    cudaEventRecord(evFork, 0);
    cudaStreamWaitEvent(sB, evFork, 0);

    k_round<<<2048, 256, 0, sB>>>(prot, (float*)pProtR, 16 * 1024 * 1152 / 4);
    k_round<<<148, 256, 0, sB>>>(W1, (float*)pW1R, 1152 * 512 / 4);
    // hid = relu(prot @ W1 + b1), tf32-rounded   [16384 x 512 x 1152]
    tf32gemm<128,128,16,64,32,1,3><<<dim3(4,128,1), 256, gemm_smem(128,128,16,3), sB>>>(
        (const float*)pProtR, (const float*)pW1R, b1, (float*)pHid, 16384, 512, 1152, 0, 0);
    k_round<<<32, 256, 0, sB>>>(W2, (float*)pW2R, 512 * 128 / 4);
    // out_prot = leaky(hid @ W2 + b2)  [16384 x 128 x 512], row remap
    tf32gemm<64,128,16,32,32,2,3><<<dim3(1,256,1), 256, gemm_smem(64,128,16,3), sB>>>(
        (const float*)pHid, (const float*)pW2R, b2, out, 16384, 128, 512, 0, 0);
    cudaEventRecord(evJoin, sB);

    // ---- GAT chain on origin stream ----
    k_round<<<16, 256>>>(W_out, (float*)pWoutR, 256 * 128 / 4);
    k_embed_gat1<<<16 * 512, 256>>>(atoms, emb_atom, W_gat, a_gat);
    k_att_rows<<<16 * 512, 256>>>((const float*)pS1, (const float*)pS2,
                                  adj, (float*)pAtt1, 4);
    // multi = elu(att1 @ Wh)   [512 x 64 x 512] x 64 batches
    tf32gemm<128,64,16,64,16,3,3><<<dim3(1,4,64), 256, gemm_smem(128,64,16,3)>>>(
        (const float*)pAtt1, (const float*)pWh, nullptr, (float*)pMulti,
        512, 64, 512, (long)512 * 512, (long)512 * 64);
    // Wh2 = multi @ W_out   [8192 x 128 x 256]
    tf32gemm<64,128,16,32,32,4,3><<<dim3(1,128,1), 256, gemm_smem(64,128,16,3)>>>(
        (const float*)pMulti, (const float*)pWoutR, nullptr, (float*)pWh2,
        8192, 128, 256, 0, 0);
    k_t12<<<16 * 512, 128>>>(a_out);
    k_att_rows<<<16 * 512, 256>>>((const float*)pT1, (const float*)pT2,
                                  adj, (float*)pAtt2, 1);
    // hp2 = att2 @ Wh2   [512 x 128 x 512] x 16 batches
    tf32gemm<64,128,16,32,32,0,3><<<dim3(1,8,16), 256, gemm_smem(64,128,16,3)>>>(
        (const float*)pAtt2, (const float*)pWh2, nullptr, (float*)pHp2,
        512, 128, 512, (long)512 * 512, (long)512 * 128);
    k_final_atoms<<<16 * 512, 128>>>(Wc, bc, out);

    // ---- join ----
    cudaStreamWaitEvent(0, evJoin, 0);
}